// round 2
// baseline (speedup 1.0000x reference)
#include <cuda_runtime.h>
#include <cuda_bf16.h>
#include <math.h>

#define BR 4
#define BB 32
#define TT 1024
#define HH 64
#define DD 128
#define NN 16
#define KK 4
#define RR 4
#define EE 32
#define LL 3
#define MAXN 0.996f

// ---------------- scratch (device globals; no allocation allowed) ----------------
__device__ float g_h[2][(size_t)BR*BB*TT*HH];     // ping-pong hidden (B,T,H) per branch
__device__ float g_xr[(size_t)BR*BB*TT*DD];
__device__ float g_z [(size_t)BR*BB*TT*DD];
__device__ float g_u [(size_t)BR*BB*TT*DD];
__device__ float g_xdbl[(size_t)BR*BB*TT*36];
__device__ float g_y [(size_t)BR*BB*TT*DD];

__device__ __forceinline__ float wsum(float v) {
    #pragma unroll
    for (int o = 16; o; o >>= 1) v += __shfl_xor_sync(0xffffffffu, v, o);
    return v;
}

// ---------------- k_embed: h0 = x * inp_W + inp_b ----------------
__global__ void k_embed(const float* __restrict__ x0, const float* __restrict__ x1,
                        const float* __restrict__ x2, const float* __restrict__ x3,
                        const float* __restrict__ iW, const float* __restrict__ ib) {
    size_t idx = (size_t)blockIdx.x * blockDim.x + threadIdx.x;
    int h  = idx & 63;
    int t  = (idx >> 6) & 1023;
    int b  = (idx >> 16) & 31;
    int br = idx >> 21;
    const float* xp = (br == 0) ? x0 : (br == 1) ? x1 : (br == 2) ? x2 : x3;
    float xv = xp[b * TT + t];
    g_h[0][idx] = xv * iW[br * HH + h] + ib[br * HH + h];
}

// ---------------- k_inproj: xz = h @ inW^T -> (xr, z) ----------------
// grid (16,32,4) block 256. Tile 64 rows x 256 outs, d-chunks of 64.
__global__ void k_inproj(const float* __restrict__ inW_all, int l, int src) {
    __shared__ float sH[64 * 64];
    __shared__ float sW[64 * 66];
    int br = blockIdx.z, b = blockIdx.y, t0 = blockIdx.x * 64;
    int tid = threadIdx.x;
    const float* Wb = inW_all + (size_t)((br * LL + l) * 2 * DD) * HH;
    const float* hb = g_h[src] + ((size_t)(br * BB + b) * TT + t0) * HH;
    for (int i = tid; i < 64 * 64; i += 256) sH[i] = hb[i];

    size_t outbase = ((size_t)(br * BB + b) * TT + t0) * DD;
    int dl2 = (tid & 31) * 2;
    int rg  = tid >> 5;  // 8 groups x 8 rows
    for (int dc = 0; dc < 4; dc++) {
        __syncthreads();
        int d0 = dc * 64;
        for (int i = tid; i < 64 * 64; i += 256) {
            int dl = i >> 6, k = i & 63;
            sW[k * 66 + dl] = Wb[(size_t)(d0 + dl) * 64 + k];
        }
        __syncthreads();
        float a0[8], a1[8];
        #pragma unroll
        for (int i = 0; i < 8; i++) { a0[i] = 0.f; a1[i] = 0.f; }
        #pragma unroll 8
        for (int k = 0; k < 64; k++) {
            float2 w = *(const float2*)&sW[k * 66 + dl2];
            #pragma unroll
            for (int i = 0; i < 8; i++) {
                float hv = sH[(rg * 8 + i) * 64 + k];
                a0[i] += w.x * hv; a1[i] += w.y * hv;
            }
        }
        int d = d0 + dl2;
        if (d < DD) {
            #pragma unroll
            for (int i = 0; i < 8; i++)
                *(float2*)&g_xr[outbase + (size_t)(rg * 8 + i) * DD + d] = make_float2(a0[i], a1[i]);
        } else {
            int dz = d - DD;
            #pragma unroll
            for (int i = 0; i < 8; i++)
                *(float2*)&g_z[outbase + (size_t)(rg * 8 + i) * DD + dz] = make_float2(a0[i], a1[i]);
        }
    }
}

// ---------------- k_conv: causal depthwise conv (K=4) + bias + silu -> u ----------------
// grid 128 (br*32+b), block 128 (d)
__global__ void k_conv(const float* __restrict__ convW, const float* __restrict__ convb, int l) {
    int br = blockIdx.x >> 5, b = blockIdx.x & 31;
    int d = threadIdx.x;
    int pl = br * LL + l;
    const float* cw = convW + (size_t)(pl * DD + d) * KK;
    float c0 = cw[0], c1 = cw[1], c2 = cw[2], c3 = cw[3];
    float bias = convb[pl * DD + d];
    size_t base = (size_t)(br * BB + b) * TT * DD + d;
    float w0 = 0.f, w1 = 0.f, w2 = 0.f;
    for (int t = 0; t < TT; t++) {
        float x = g_xr[base + (size_t)t * DD];
        float v = c0 * w0 + c1 * w1 + c2 * w2 + c3 * x + bias;
        g_u[base + (size_t)t * DD] = v / (1.f + __expf(-v));
        w0 = w1; w1 = w2; w2 = x;
    }
}

// ---------------- k_xdbl: x_dbl = u @ xpW^T (36 outs) ----------------
// grid (16,32,4) block 256
__global__ void k_xdbl(const float* __restrict__ xpW, int l) {
    __shared__ float sU[64 * 129];
    __shared__ float sW[64 * 36];
    int br = blockIdx.z, b = blockIdx.y, t0 = blockIdx.x * 64;
    int tid = threadIdx.x;
    const float* Wb = xpW + (size_t)(br * LL + l) * 36 * DD;
    size_t ubase = ((size_t)(br * BB + b) * TT + t0) * DD;
    for (int i = tid; i < 64 * 128; i += 256) {
        int r = i >> 7, k = i & 127;
        sU[r * 129 + k] = g_u[ubase + i];
    }
    int r = tid >> 2;
    int eg = tid & 3;
    float acc[9];
    #pragma unroll
    for (int j = 0; j < 9; j++) acc[j] = 0.f;
    for (int kc = 0; kc < 2; kc++) {
        __syncthreads();
        for (int i = tid; i < 64 * 36; i += 256) {
            int kl = i & 63, e = i >> 6;
            if (e < 36) sW[kl * 36 + e] = Wb[(size_t)e * DD + kc * 64 + kl];
        }
        __syncthreads();
        #pragma unroll 4
        for (int kl = 0; kl < 64; kl++) {
            float su = sU[r * 129 + kc * 64 + kl];
            #pragma unroll
            for (int j = 0; j < 9; j++) acc[j] += su * sW[kl * 36 + eg * 9 + j];
        }
    }
    size_t ob = ((size_t)(br * BB + b) * TT + t0 + r) * 36;
    #pragma unroll
    for (int j = 0; j < 9; j++) g_xdbl[ob + eg * 9 + j] = acc[j];
}

// ---------------- k_scan: fused softplus(dt) + selective scan + D skip ----------------
// grid 128 (br*32+b), block 128 (d)
__global__ void k_scan(const float* __restrict__ A_log, const float* __restrict__ Dp_all,
                       const float* __restrict__ dtW, const float* __restrict__ dtb, int l) {
    __shared__ float sXD[64][36];
    int br = blockIdx.x >> 5, b = blockIdx.x & 31;
    int d = threadIdx.x;
    int pl = br * LL + l;
    float a[NN];
    #pragma unroll
    for (int n = 0; n < NN; n++) a[n] = -__expf(A_log[(size_t)(pl * DD + d) * NN + n]);
    float dpv = Dp_all[pl * DD + d];
    const float* dw = dtW + (size_t)(pl * DD + d) * RR;
    float w0 = dw[0], w1 = dw[1], w2 = dw[2], w3 = dw[3];
    float db = dtb[pl * DD + d];
    float h[NN];
    #pragma unroll
    for (int n = 0; n < NN; n++) h[n] = 0.f;
    size_t rowbase = (size_t)(br * BB + b) * TT;
    for (int chunk = 0; chunk < TT / 64; chunk++) {
        __syncthreads();
        for (int i = d; i < 64 * 36; i += 128) {
            int rr = i / 36, c = i - rr * 36;
            sXD[rr][c] = g_xdbl[(rowbase + chunk * 64 + rr) * 36 + c];
        }
        __syncthreads();
        for (int s = 0; s < 64; s++) {
            size_t t = chunk * 64 + s;
            float uv = g_u[(rowbase + t) * DD + d];
            float dtp = w0 * sXD[s][0] + w1 * sXD[s][1] + w2 * sXD[s][2] + w3 * sXD[s][3] + db;
            float dt = (dtp > 20.f) ? dtp : log1pf(__expf(dtp));
            float du = dt * uv;
            float y = dpv * uv;
            #pragma unroll
            for (int n = 0; n < NN; n++) {
                float dA = __expf(dt * a[n]);
                h[n] = dA * h[n] + du * sXD[s][4 + n];
                y += h[n] * sXD[s][20 + n];
            }
            g_y[(rowbase + t) * DD + d] = y;
        }
    }
}

// ---------------- k_outgemm: h_next = (y * silu(z)) @ outW^T ----------------
// grid (32,32,4) block 256; 32 rows, K=128 in 2 chunks
__global__ void k_outgemm(const float* __restrict__ oW, int l, int dst) {
    __shared__ float sP[32 * 128];
    __shared__ float sWc[64 * 66];
    int br = blockIdx.z, b = blockIdx.y, t0 = blockIdx.x * 32;
    int tid = threadIdx.x;
    size_t base = ((size_t)(br * BB + b) * TT + t0) * DD;
    for (int i = tid; i < 32 * 128; i += 256) {
        float zv = g_z[base + i];
        sP[i] = g_y[base + i] * (zv / (1.f + __expf(-zv)));
    }
    const float* Wb = oW + (size_t)(br * LL + l) * HH * DD;
    int hl2 = (tid & 31) * 2, rg = tid >> 5;  // 8 groups x 4 rows
    float a0[4] = {0,0,0,0}, a1[4] = {0,0,0,0};
    for (int kc = 0; kc < 2; kc++) {
        __syncthreads();
        for (int i = tid; i < 64 * 64; i += 256) {
            int kl = i & 63, hh = i >> 6;
            sWc[kl * 66 + hh] = Wb[(size_t)hh * DD + kc * 64 + kl];
        }
        __syncthreads();
        #pragma unroll 4
        for (int kl = 0; kl < 64; kl++) {
            float2 w = *(const float2*)&sWc[kl * 66 + hl2];
            #pragma unroll
            for (int i = 0; i < 4; i++) {
                float pv = sP[(rg * 4 + i) * 128 + kc * 64 + kl];
                a0[i] += w.x * pv; a1[i] += w.y * pv;
            }
        }
    }
    float* hb = g_h[dst] + ((size_t)(br * BB + b) * TT + t0) * HH;
    #pragma unroll
    for (int i = 0; i < 4; i++)
        *(float2*)&hb[(size_t)(rg * 4 + i) * HH + hl2] = make_float2(a0[i], a1[i]);
}

// ---------------- k_head: outp proj + tanh + expmap0 + projx -> out slots 0..3 ----------------
// grid (16,32,4) block 256
__global__ void k_head(const float* __restrict__ opW, const float* __restrict__ opb,
                       float* __restrict__ out, int src) {
    __shared__ float sH[64 * 64];
    __shared__ float sW[64 * 33];
    __shared__ float sB[32];
    int br = blockIdx.z, b = blockIdx.y, t0 = blockIdx.x * 64;
    int tid = threadIdx.x;
    const float* hb = g_h[src] + ((size_t)(br * BB + b) * TT + t0) * HH;
    for (int i = tid; i < 4096; i += 256) sH[i] = hb[i];
    for (int i = tid; i < 2048; i += 256) {
        int e = i >> 6, hh = i & 63;
        sW[hh * 33 + e] = opW[(size_t)br * EE * HH + i];
    }
    if (tid < 32) sB[tid] = opb[br * EE + tid];
    __syncthreads();
    int e = tid & 31, rg = tid >> 5;
    #pragma unroll
    for (int i = 0; i < 8; i++) {
        int r = rg * 8 + i;
        float acc = sB[e];
        #pragma unroll
        for (int hh = 0; hh < 64; hh++) acc += sH[r * 64 + hh] * sW[hh * 33 + e];
        float z = tanhf(acc);
        float n2 = wsum(z * z);
        float n = sqrtf(fmaxf(n2, 1e-15f));
        float zh = z * (tanhf(n) / n);
        float n2b = wsum(zh * zh);
        float nb = sqrtf(fmaxf(n2b, 1e-15f));
        if (nb > MAXN) zh *= MAXN / nb;
        out[(size_t)br * BB * TT * EE + ((size_t)(b * TT + t0 + r)) * EE + e] = zh;
    }
}

// ---------------- k_mobius: comb = projx(mob(mob(t, mob(w,d)), r)) -> slot 4 ----------------
__device__ __forceinline__ float mob(float x, float y) {
    float x2 = wsum(x * x);
    float y2 = wsum(y * y);
    float xy = wsum(x * y);
    float num = (1.f + 2.f * xy + y2) * x + (1.f - x2) * y;
    float den = 1.f + 2.f * xy + x2 * y2;
    return num / fmaxf(den, 1e-15f);
}

__global__ void k_mobius(float* __restrict__ out) {
    int warp = threadIdx.x >> 5, e = threadIdx.x & 31;
    size_t row = (size_t)blockIdx.x * 8 + warp;   // b*T + t
    size_t S = (size_t)BB * TT * EE;
    float tv = out[0 * S + row * EE + e];
    float wv = out[1 * S + row * EE + e];
    float dv = out[2 * S + row * EE + e];
    float rv = out[3 * S + row * EE + e];
    float m = mob(wv, dv);
    m = mob(tv, m);
    m = mob(m, rv);
    float n2 = wsum(m * m);
    float n = sqrtf(fmaxf(n2, 1e-15f));
    if (n > MAXN) m *= MAXN / n;
    out[4 * S + row * EE + e] = m;
}

// ---------------- launch ----------------
extern "C" void kernel_launch(void* const* d_in, const int* in_sizes, int n_in,
                              void* d_out, int out_size) {
    const float* trend = (const float*)d_in[0];
    const float* sweek = (const float*)d_in[1];
    const float* sday  = (const float*)d_in[2];
    const float* resid = (const float*)d_in[3];
    const float* inp_W = (const float*)d_in[4];
    const float* inp_b = (const float*)d_in[5];
    const float* in_proj_W = (const float*)d_in[6];
    const float* conv_W = (const float*)d_in[7];
    const float* conv_b = (const float*)d_in[8];
    const float* xproj_W = (const float*)d_in[9];
    const float* dt_W = (const float*)d_in[10];
    const float* dt_b = (const float*)d_in[11];
    const float* A_log = (const float*)d_in[12];
    const float* D_skip = (const float*)d_in[13];
    const float* out_W = (const float*)d_in[14];
    const float* outp_W = (const float*)d_in[15];
    const float* outp_b = (const float*)d_in[16];
    float* out = (float*)d_out;

    k_embed<<<(BR * BB * TT * HH) / 256, 256>>>(trend, sweek, sday, resid, inp_W, inp_b);

    for (int l = 0; l < LL; l++) {
        int src = l & 1, dst = (l + 1) & 1;
        k_inproj<<<dim3(16, 32, 4), 256>>>(in_proj_W, l, src);
        k_conv<<<128, 128>>>(conv_W, conv_b, l);
        k_xdbl<<<dim3(16, 32, 4), 256>>>(xproj_W, l);
        k_scan<<<128, 128>>>(A_log, D_skip, dt_W, dt_b, l);
        k_outgemm<<<dim3(32, 32, 4), 256>>>(out_W, l, dst);
    }

    k_head<<<dim3(16, 32, 4), 256>>>(outp_W, outp_b, out, LL & 1);
    k_mobius<<<(BB * TT) / 8, 256>>>(out);
}

// round 3
// speedup vs baseline: 1.1354x; 1.1354x over previous
#include <cuda_runtime.h>
#include <cuda_bf16.h>
#include <math.h>

#define BR 4
#define BB 32
#define TT 1024
#define HH 64
#define DD 128
#define NN 16
#define KK 4
#define RR 4
#define EE 32
#define LL 3
#define MAXN 0.996f

typedef unsigned long long u64;

// ---------------- f32x2 packed-FMA helpers (sm_103a FFMA2 path) ----------------
__device__ __forceinline__ u64 pk2(float x, float y) {
    u64 r; asm("mov.b64 %0, {%1, %2};" : "=l"(r) : "f"(x), "f"(y)); return r;
}
__device__ __forceinline__ float2 upk2(u64 v) {
    float2 r; asm("mov.b64 {%0, %1}, %2;" : "=f"(r.x), "=f"(r.y) : "l"(v)); return r;
}
__device__ __forceinline__ void fma2(u64& d, u64 a, u64 b) {
    asm("fma.rn.f32x2 %0, %1, %2, %0;" : "+l"(d) : "l"(a), "l"(b));
}
__device__ __forceinline__ u64 mul2(u64 a, u64 b) {
    u64 r; asm("mul.rn.f32x2 %0, %1, %2;" : "=l"(r) : "l"(a), "l"(b)); return r;
}
__device__ __forceinline__ float ex2f(float x) {
    float r; asm("ex2.approx.f32 %0, %1;" : "=f"(r) : "f"(x)); return r;
}
__device__ __forceinline__ float lg2f(float x) {
    float r; asm("lg2.approx.f32 %0, %1;" : "=f"(r) : "f"(x)); return r;
}

// ---------------- scratch (device globals; no allocation allowed) ----------------
__device__ float g_h[2][(size_t)BR*BB*TT*HH];
__device__ float g_xr[(size_t)BR*BB*TT*DD];
__device__ float g_z [(size_t)BR*BB*TT*DD];
__device__ float g_u [(size_t)BR*BB*TT*DD];
__device__ float g_xdbl[(size_t)BR*BB*TT*36];
__device__ float g_y [(size_t)BR*BB*TT*DD];

__device__ __forceinline__ float wsum(float v) {
    #pragma unroll
    for (int o = 16; o; o >>= 1) v += __shfl_xor_sync(0xffffffffu, v, o);
    return v;
}

// ---------------- k_embed: h0 = x * inp_W + inp_b ----------------
__global__ void k_embed(const float* __restrict__ x0, const float* __restrict__ x1,
                        const float* __restrict__ x2, const float* __restrict__ x3,
                        const float* __restrict__ iW, const float* __restrict__ ib) {
    size_t idx = (size_t)blockIdx.x * blockDim.x + threadIdx.x;
    int h  = idx & 63;
    int t  = (idx >> 6) & 1023;
    int b  = (idx >> 16) & 31;
    int br = idx >> 21;
    const float* xp = (br == 0) ? x0 : (br == 1) ? x1 : (br == 2) ? x2 : x3;
    float xv = xp[b * TT + t];
    g_h[0][idx] = xv * iW[br * HH + h] + ib[br * HH + h];
}

// ---------------- k_inproj: xz = h @ inW^T -> (xr, z) ----------------
// grid (16,32,4) block 256, dyn smem. Tile 64 rows x 256 outs, K=64, 2 col-chunks.
__global__ void k_inproj(const float* __restrict__ inW_all, int l, int src) {
    extern __shared__ float sm[];
    float* sHt = sm;              // [64][68] transposed: sHt[k*68 + row]
    float* sW  = sm + 64 * 68;    // [64][132]: sW[k*132 + dl]
    int br = blockIdx.z, b = blockIdx.y, t0 = blockIdx.x * 64;
    int tid = threadIdx.x;
    const float* Wb = inW_all + (size_t)((br * LL + l) * 2 * DD) * HH;
    const float* hb = g_h[src] + ((size_t)(br * BB + b) * TT + t0) * HH;
    for (int i = tid; i < 4096; i += 256) sHt[(i & 63) * 68 + (i >> 6)] = hb[i];

    size_t outbase = ((size_t)(br * BB + b) * TT + t0) * DD;
    int rowg = tid & 7, colg = tid >> 3;   // 8 rows each x 32 colgroups (4 cols)
    for (int dc = 0; dc < 2; dc++) {
        __syncthreads();
        int d0 = dc * 128;
        for (int i = tid; i < 8192; i += 256) {
            int k = i & 63, dl = i >> 6;
            sW[k * 132 + dl] = Wb[(size_t)(d0 + dl) * HH + k];
        }
        __syncthreads();
        u64 a0[8], a1[8];
        #pragma unroll
        for (int r = 0; r < 8; r++) { a0[r] = 0ull; a1[r] = 0ull; }
        #pragma unroll 4
        for (int k = 0; k < 64; k++) {
            float4 hA = *(const float4*)&sHt[k * 68 + rowg * 8];
            float4 hB = *(const float4*)&sHt[k * 68 + rowg * 8 + 4];
            float4 w  = *(const float4*)&sW [k * 132 + colg * 4];
            u64 w01 = pk2(w.x, w.y), w23 = pk2(w.z, w.w);
            float hv[8] = {hA.x, hA.y, hA.z, hA.w, hB.x, hB.y, hB.z, hB.w};
            #pragma unroll
            for (int r = 0; r < 8; r++) {
                u64 hp = pk2(hv[r], hv[r]);
                fma2(a0[r], hp, w01);
                fma2(a1[r], hp, w23);
            }
        }
        float* dst = (dc == 0) ? g_xr : g_z;
        #pragma unroll
        for (int r = 0; r < 8; r++) {
            float2 p0 = upk2(a0[r]), p1 = upk2(a1[r]);
            *(float4*)&dst[outbase + (size_t)(rowg * 8 + r) * DD + colg * 4] =
                make_float4(p0.x, p0.y, p1.x, p1.y);
        }
    }
}

// ---------------- k_convxdbl: fused conv+silu (-> u) + x_dbl GEMM ----------------
// grid (8,32,4) block 192, dyn smem. Tile 128 rows x 36 outs, K=128.
__global__ void k_convxdbl(const float* __restrict__ convW, const float* __restrict__ convb,
                           const float* __restrict__ xpW, int l) {
    extern __shared__ float sm[];
    float* sUt = sm;                    // [128][132]: sUt[d*132 + r]
    float* sW  = sm + 128 * 132;        // [128][38]:  sW[k*38 + e]
    float* scw = sW + 128 * 38;         // [128][4]
    float* sb  = scw + 512;             // [128]
    int br = blockIdx.z, b = blockIdx.y, t0 = blockIdx.x * 128;
    int tid = threadIdx.x;
    int pl = br * LL + l;
    for (int i = tid; i < 512; i += 192) scw[i] = convW[(size_t)pl * DD * KK + i];
    for (int i = tid; i < 128; i += 192) sb[i] = convb[pl * DD + i];
    __syncthreads();
    size_t rowbase = (size_t)(br * BB + b) * TT;
    const float LOG2E = 1.4426950408889634f;
    for (int i = tid; i < 16384; i += 192) {
        int r = i >> 7, d = i & 127;
        int t = t0 + r;
        float x0 = (t >= 3) ? g_xr[(rowbase + t - 3) * DD + d] : 0.f;
        float x1 = (t >= 2) ? g_xr[(rowbase + t - 2) * DD + d] : 0.f;
        float x2 = (t >= 1) ? g_xr[(rowbase + t - 1) * DD + d] : 0.f;
        float x3 = g_xr[(rowbase + t) * DD + d];
        float v = scw[d * 4 + 0] * x0 + scw[d * 4 + 1] * x1 + scw[d * 4 + 2] * x2
                + scw[d * 4 + 3] * x3 + sb[d];
        float uu = v / (1.f + ex2f(-v * LOG2E));
        g_u[(rowbase + t) * DD + d] = uu;
        sUt[d * 132 + r] = uu;
    }
    const float* Wb = xpW + (size_t)pl * 36 * DD;
    for (int i = tid; i < 4608; i += 192) {
        int e = i >> 7, k = i & 127;
        sW[k * 38 + e] = Wb[(size_t)e * DD + k];
    }
    __syncthreads();
    int rowg = tid & 31, colg = tid >> 5;   // 32 rowgroups (4 rows) x 6 colgroups (6 cols)
    u64 acc[4][3];
    #pragma unroll
    for (int r = 0; r < 4; r++)
        #pragma unroll
        for (int p = 0; p < 3; p++) acc[r][p] = 0ull;
    #pragma unroll 2
    for (int k = 0; k < 128; k++) {
        float4 h4 = *(const float4*)&sUt[k * 132 + rowg * 4];
        u64 w0 = *(const u64*)&sW[k * 38 + colg * 6];
        u64 w1 = *(const u64*)&sW[k * 38 + colg * 6 + 2];
        u64 w2 = *(const u64*)&sW[k * 38 + colg * 6 + 4];
        float hv[4] = {h4.x, h4.y, h4.z, h4.w};
        #pragma unroll
        for (int r = 0; r < 4; r++) {
            u64 hp = pk2(hv[r], hv[r]);
            fma2(acc[r][0], hp, w0);
            fma2(acc[r][1], hp, w1);
            fma2(acc[r][2], hp, w2);
        }
    }
    #pragma unroll
    for (int r = 0; r < 4; r++) {
        size_t ob = (rowbase + t0 + rowg * 4 + r) * 36 + colg * 6;
        #pragma unroll
        for (int p = 0; p < 3; p++) {
            float2 v = upk2(acc[r][p]);
            *(float2*)&g_xdbl[ob + 2 * p] = v;
        }
    }
}

// ---------------- k_scan: fused softplus(dt) + selective scan + D skip ----------------
// grid 128 (br*32+b), block 128 (d)
__global__ void k_scan(const float* __restrict__ A_log, const float* __restrict__ Dp_all,
                       const float* __restrict__ dtW, const float* __restrict__ dtb, int l) {
    __shared__ float sXD[64 * 36];
    int br = blockIdx.x >> 5, b = blockIdx.x & 31;
    int d = threadIdx.x;
    int pl = br * LL + l;
    const float LOG2E = 1.4426950408889634f;
    const float LN2 = 0.6931471805599453f;
    u64 a2[8];
    #pragma unroll
    for (int p = 0; p < 8; p++) {
        float lo = -__expf(A_log[(size_t)(pl * DD + d) * NN + 2 * p    ]) * LOG2E;
        float hi = -__expf(A_log[(size_t)(pl * DD + d) * NN + 2 * p + 1]) * LOG2E;
        a2[p] = pk2(lo, hi);
    }
    float dpv = Dp_all[pl * DD + d];
    const float* dw = dtW + (size_t)(pl * DD + d) * RR;
    float w0 = dw[0], w1 = dw[1], w2 = dw[2], w3 = dw[3];
    float db = dtb[pl * DD + d];
    u64 h2[8];
    #pragma unroll
    for (int p = 0; p < 8; p++) h2[p] = 0ull;
    size_t rowbase = (size_t)(br * BB + b) * TT;
    for (int chunk = 0; chunk < TT / 64; chunk++) {
        __syncthreads();
        for (int i = d; i < 64 * 36; i += 128)
            sXD[i] = g_xdbl[(rowbase + chunk * 64) * 36 + i];
        __syncthreads();
        for (int s = 0; s < 64; s++) {
            const float* xd = &sXD[s * 36];
            float4 x4 = *(const float4*)xd;
            float dtp = w0 * x4.x + w1 * x4.y + w2 * x4.z + w3 * x4.w + db;
            float e = ex2f(dtp * LOG2E);
            float dt = (dtp > 15.f) ? dtp : LN2 * lg2f(1.f + e);
            size_t t = chunk * 64 + s;
            float uv = g_u[(rowbase + t) * DD + d];
            float du = dt * uv;
            u64 du2 = pk2(du, du);
            u64 dt2 = pk2(dt, dt);
            float y = dpv * uv;
            u64 y2 = 0ull;
            #pragma unroll
            for (int p = 0; p < 8; p++) {
                u64 arg = mul2(dt2, a2[p]);
                float2 av = upk2(arg);
                u64 dA2 = pk2(ex2f(av.x), ex2f(av.y));
                u64 B2 = *(const u64*)&xd[4 + 2 * p];
                u64 C2 = *(const u64*)&xd[20 + 2 * p];
                u64 t2 = mul2(du2, B2);
                fma2(t2, dA2, h2[p]);      // t2 = dA*h + du*B
                h2[p] = t2;
                fma2(y2, t2, C2);          // y2 += h*C
            }
            float2 yv = upk2(y2);
            g_y[(rowbase + t) * DD + d] = y + yv.x + yv.y;
        }
    }
}

// ---------------- k_outgemm: h_next = (y * silu(z)) @ outW^T ----------------
// grid (8,32,4) block 256, dyn smem. Tile 128 rows x 64 outs, K=128.
__global__ void k_outgemm(const float* __restrict__ oW, int l, int dst) {
    extern __shared__ float sm[];
    float* sPt = sm;                 // [128][132]: sPt[d*132 + r]
    float* sW  = sm + 128 * 132;     // [128][66]:  sW[k*66 + hh]
    int br = blockIdx.z, b = blockIdx.y, t0 = blockIdx.x * 128;
    int tid = threadIdx.x;
    const float LOG2E = 1.4426950408889634f;
    size_t base = ((size_t)(br * BB + b) * TT + t0) * DD;
    for (int i = tid; i < 16384; i += 256) {
        int r = i >> 7, dd = i & 127;
        float zv = g_z[base + i];
        float p = g_y[base + i] * zv / (1.f + ex2f(-zv * LOG2E));
        sPt[dd * 132 + r] = p;
    }
    const float* Wb = oW + (size_t)(br * LL + l) * HH * DD;
    for (int i = tid; i < 8192; i += 256) {
        int hh = i >> 7, k = i & 127;
        sW[k * 66 + hh] = Wb[(size_t)hh * DD + k];
    }
    __syncthreads();
    int rowg = tid & 31, colg = tid >> 5;   // 32 rowgroups (4 rows) x 8 colgroups (8 cols)
    u64 acc[4][4];
    #pragma unroll
    for (int r = 0; r < 4; r++)
        #pragma unroll
        for (int p = 0; p < 4; p++) acc[r][p] = 0ull;
    #pragma unroll 2
    for (int k = 0; k < 128; k++) {
        float4 h4 = *(const float4*)&sPt[k * 132 + rowg * 4];
        u64 w0 = *(const u64*)&sW[k * 66 + colg * 8];
        u64 w1 = *(const u64*)&sW[k * 66 + colg * 8 + 2];
        u64 w2 = *(const u64*)&sW[k * 66 + colg * 8 + 4];
        u64 w3 = *(const u64*)&sW[k * 66 + colg * 8 + 6];
        float hv[4] = {h4.x, h4.y, h4.z, h4.w};
        #pragma unroll
        for (int r = 0; r < 4; r++) {
            u64 hp = pk2(hv[r], hv[r]);
            fma2(acc[r][0], hp, w0);
            fma2(acc[r][1], hp, w1);
            fma2(acc[r][2], hp, w2);
            fma2(acc[r][3], hp, w3);
        }
    }
    float* hb = g_h[dst] + ((size_t)(br * BB + b) * TT + t0) * HH;
    #pragma unroll
    for (int r = 0; r < 4; r++) {
        int row = rowg * 4 + r;
        float2 p0 = upk2(acc[r][0]), p1 = upk2(acc[r][1]);
        float2 p2 = upk2(acc[r][2]), p3 = upk2(acc[r][3]);
        *(float4*)&hb[(size_t)row * HH + colg * 8]     = make_float4(p0.x, p0.y, p1.x, p1.y);
        *(float4*)&hb[(size_t)row * HH + colg * 8 + 4] = make_float4(p2.x, p2.y, p3.x, p3.y);
    }
}

// ---------------- k_head: outp proj + tanh + expmap0 + projx -> out slots 0..3 ----------------
__global__ void k_head(const float* __restrict__ opW, const float* __restrict__ opb,
                       float* __restrict__ out, int src) {
    __shared__ float sH[64 * 64];
    __shared__ float sW[64 * 33];
    __shared__ float sB[32];
    int br = blockIdx.z, b = blockIdx.y, t0 = blockIdx.x * 64;
    int tid = threadIdx.x;
    const float* hb = g_h[src] + ((size_t)(br * BB + b) * TT + t0) * HH;
    for (int i = tid; i < 4096; i += 256) sH[i] = hb[i];
    for (int i = tid; i < 2048; i += 256) {
        int e = i >> 6, hh = i & 63;
        sW[hh * 33 + e] = opW[(size_t)br * EE * HH + i];
    }
    if (tid < 32) sB[tid] = opb[br * EE + tid];
    __syncthreads();
    int e = tid & 31, rg = tid >> 5;
    #pragma unroll
    for (int i = 0; i < 8; i++) {
        int r = rg * 8 + i;
        float acc = sB[e];
        #pragma unroll
        for (int hh = 0; hh < 64; hh++) acc += sH[r * 64 + hh] * sW[hh * 33 + e];
        float z = tanhf(acc);
        float n2 = wsum(z * z);
        float n = sqrtf(fmaxf(n2, 1e-15f));
        float zh = z * (tanhf(n) / n);
        float n2b = wsum(zh * zh);
        float nb = sqrtf(fmaxf(n2b, 1e-15f));
        if (nb > MAXN) zh *= MAXN / nb;
        out[(size_t)br * BB * TT * EE + ((size_t)(b * TT + t0 + r)) * EE + e] = zh;
    }
}

// ---------------- k_mobius ----------------
__device__ __forceinline__ float mob(float x, float y) {
    float x2 = wsum(x * x);
    float y2 = wsum(y * y);
    float xy = wsum(x * y);
    float num = (1.f + 2.f * xy + y2) * x + (1.f - x2) * y;
    float den = 1.f + 2.f * xy + x2 * y2;
    return num / fmaxf(den, 1e-15f);
}

__global__ void k_mobius(float* __restrict__ out) {
    int warp = threadIdx.x >> 5, e = threadIdx.x & 31;
    size_t row = (size_t)blockIdx.x * 8 + warp;
    size_t S = (size_t)BB * TT * EE;
    float tv = out[0 * S + row * EE + e];
    float wv = out[1 * S + row * EE + e];
    float dv = out[2 * S + row * EE + e];
    float rv = out[3 * S + row * EE + e];
    float m = mob(wv, dv);
    m = mob(tv, m);
    m = mob(m, rv);
    float n2 = wsum(m * m);
    float n = sqrtf(fmaxf(n2, 1e-15f));
    if (n > MAXN) m *= MAXN / n;
    out[4 * S + row * EE + e] = m;
}

// ---------------- launch ----------------
extern "C" void kernel_launch(void* const* d_in, const int* in_sizes, int n_in,
                              void* d_out, int out_size) {
    const float* trend = (const float*)d_in[0];
    const float* sweek = (const float*)d_in[1];
    const float* sday  = (const float*)d_in[2];
    const float* resid = (const float*)d_in[3];
    const float* inp_W = (const float*)d_in[4];
    const float* inp_b = (const float*)d_in[5];
    const float* in_proj_W = (const float*)d_in[6];
    const float* conv_W = (const float*)d_in[7];
    const float* conv_b = (const float*)d_in[8];
    const float* xproj_W = (const float*)d_in[9];
    const float* dt_W = (const float*)d_in[10];
    const float* dt_b = (const float*)d_in[11];
    const float* A_log = (const float*)d_in[12];
    const float* D_skip = (const float*)d_in[13];
    const float* out_W = (const float*)d_in[14];
    const float* outp_W = (const float*)d_in[15];
    const float* outp_b = (const float*)d_in[16];
    float* out = (float*)d_out;

    const int SM_INPROJ = (64 * 68 + 64 * 132) * 4;                      // 51200
    const int SM_CONVXD = (128 * 132 + 128 * 38 + 512 + 128) * 4;        // 89600
    const int SM_OUTG   = (128 * 132 + 128 * 66) * 4;                    // 101376
    cudaFuncSetAttribute(k_inproj,   cudaFuncAttributeMaxDynamicSharedMemorySize, SM_INPROJ);
    cudaFuncSetAttribute(k_convxdbl, cudaFuncAttributeMaxDynamicSharedMemorySize, SM_CONVXD);
    cudaFuncSetAttribute(k_outgemm,  cudaFuncAttributeMaxDynamicSharedMemorySize, SM_OUTG);

    k_embed<<<(BR * BB * TT * HH) / 256, 256>>>(trend, sweek, sday, resid, inp_W, inp_b);

    for (int l = 0; l < LL; l++) {
        int src = l & 1, dst = (l + 1) & 1;
        k_inproj<<<dim3(16, 32, 4), 256, SM_INPROJ>>>(in_proj_W, l, src);
        k_convxdbl<<<dim3(8, 32, 4), 192, SM_CONVXD>>>(conv_W, conv_b, xproj_W, l);
        k_scan<<<128, 128>>>(A_log, D_skip, dt_W, dt_b, l);
        k_outgemm<<<dim3(8, 32, 4), 256, SM_OUTG>>>(out_W, l, dst);
    }

    k_head<<<dim3(16, 32, 4), 256>>>(outp_W, outp_b, out, LL & 1);
    k_mobius<<<(BB * TT) / 8, 256>>>(out);
}

// round 4
// speedup vs baseline: 1.5559x; 1.3704x over previous
#include <cuda_runtime.h>
#include <cuda_bf16.h>
#include <math.h>

#define BR 4
#define BB 32
#define TT 1024
#define HH 64
#define DD 128
#define NN 16
#define KK 4
#define RR 4
#define EE 32
#define LL 3
#define CH 16          // scan chunks
#define CS 64          // steps per chunk
#define MAXN 0.996f

typedef unsigned long long u64;

// ---------------- f32x2 packed-FMA helpers (sm_103a FFMA2 path) ----------------
__device__ __forceinline__ u64 pk2(float x, float y) {
    u64 r; asm("mov.b64 %0, {%1, %2};" : "=l"(r) : "f"(x), "f"(y)); return r;
}
__device__ __forceinline__ float2 upk2(u64 v) {
    float2 r; asm("mov.b64 {%0, %1}, %2;" : "=f"(r.x), "=f"(r.y) : "l"(v)); return r;
}
__device__ __forceinline__ void fma2(u64& d, u64 a, u64 b) {
    asm("fma.rn.f32x2 %0, %1, %2, %0;" : "+l"(d) : "l"(a), "l"(b));
}
__device__ __forceinline__ u64 mul2(u64 a, u64 b) {
    u64 r; asm("mul.rn.f32x2 %0, %1, %2;" : "=l"(r) : "l"(a), "l"(b)); return r;
}
__device__ __forceinline__ float ex2f(float x) {
    float r; asm("ex2.approx.f32 %0, %1;" : "=f"(r) : "f"(x)); return r;
}
__device__ __forceinline__ float lg2f(float x) {
    float r; asm("lg2.approx.f32 %0, %1;" : "=f"(r) : "f"(x)); return r;
}

// ---------------- scratch (device globals; no allocation allowed) ----------------
__device__ float g_h[2][(size_t)BR*BB*TT*HH];
__device__ float g_xr[(size_t)BR*BB*TT*DD];
__device__ float g_z [(size_t)BR*BB*TT*DD];
__device__ float g_u [(size_t)BR*BB*TT*DD];
__device__ float g_xdbl[(size_t)BR*BB*TT*36];
__device__ float g_y [(size_t)BR*BB*TT*DD];
// chunked-scan carries: [bb][chunk][d][n]
__device__ float g_hfin[(size_t)BR*BB*CH*DD*NN];
__device__ float g_pfin[(size_t)BR*BB*CH*DD*NN];
__device__ float g_hin [(size_t)BR*BB*CH*DD*NN];

__device__ __forceinline__ float wsum(float v) {
    #pragma unroll
    for (int o = 16; o; o >>= 1) v += __shfl_xor_sync(0xffffffffu, v, o);
    return v;
}

// ---------------- k_embed ----------------
__global__ void k_embed(const float* __restrict__ x0, const float* __restrict__ x1,
                        const float* __restrict__ x2, const float* __restrict__ x3,
                        const float* __restrict__ iW, const float* __restrict__ ib) {
    size_t idx = (size_t)blockIdx.x * blockDim.x + threadIdx.x;
    int h  = idx & 63;
    int t  = (idx >> 6) & 1023;
    int b  = (idx >> 16) & 31;
    int br = idx >> 21;
    const float* xp = (br == 0) ? x0 : (br == 1) ? x1 : (br == 2) ? x2 : x3;
    float xv = xp[b * TT + t];
    g_h[0][idx] = xv * iW[br * HH + h] + ib[br * HH + h];
}

// ---------------- k_inproj ----------------
__global__ void k_inproj(const float* __restrict__ inW_all, int l, int src) {
    extern __shared__ float sm[];
    float* sHt = sm;              // [64][68]
    float* sW  = sm + 64 * 68;    // [64][132]
    int br = blockIdx.z, b = blockIdx.y, t0 = blockIdx.x * 64;
    int tid = threadIdx.x;
    const float* Wb = inW_all + (size_t)((br * LL + l) * 2 * DD) * HH;
    const float* hb = g_h[src] + ((size_t)(br * BB + b) * TT + t0) * HH;
    for (int i = tid; i < 4096; i += 256) sHt[(i & 63) * 68 + (i >> 6)] = hb[i];

    size_t outbase = ((size_t)(br * BB + b) * TT + t0) * DD;
    int rowg = tid & 7, colg = tid >> 3;
    for (int dc = 0; dc < 2; dc++) {
        __syncthreads();
        int d0 = dc * 128;
        for (int i = tid; i < 8192; i += 256) {
            int k = i & 63, dl = i >> 6;
            sW[k * 132 + dl] = Wb[(size_t)(d0 + dl) * HH + k];
        }
        __syncthreads();
        u64 a0[8], a1[8];
        #pragma unroll
        for (int r = 0; r < 8; r++) { a0[r] = 0ull; a1[r] = 0ull; }
        #pragma unroll 4
        for (int k = 0; k < 64; k++) {
            float4 hA = *(const float4*)&sHt[k * 68 + rowg * 8];
            float4 hB = *(const float4*)&sHt[k * 68 + rowg * 8 + 4];
            float4 w  = *(const float4*)&sW [k * 132 + colg * 4];
            u64 w01 = pk2(w.x, w.y), w23 = pk2(w.z, w.w);
            float hv[8] = {hA.x, hA.y, hA.z, hA.w, hB.x, hB.y, hB.z, hB.w};
            #pragma unroll
            for (int r = 0; r < 8; r++) {
                u64 hp = pk2(hv[r], hv[r]);
                fma2(a0[r], hp, w01);
                fma2(a1[r], hp, w23);
            }
        }
        float* dst = (dc == 0) ? g_xr : g_z;
        #pragma unroll
        for (int r = 0; r < 8; r++) {
            float2 p0 = upk2(a0[r]), p1 = upk2(a1[r]);
            *(float4*)&dst[outbase + (size_t)(rowg * 8 + r) * DD + colg * 4] =
                make_float4(p0.x, p0.y, p1.x, p1.y);
        }
    }
}

// ---------------- k_convxdbl: fused conv+silu (-> u) + x_dbl GEMM ----------------
__global__ void k_convxdbl(const float* __restrict__ convW, const float* __restrict__ convb,
                           const float* __restrict__ xpW, int l) {
    extern __shared__ float sm[];
    float* sUt = sm;                    // [128][132]
    float* sW  = sm + 128 * 132;        // [128][38]
    float* scw = sW + 128 * 38;         // [128][4]
    float* sb  = scw + 512;             // [128]
    int br = blockIdx.z, b = blockIdx.y, t0 = blockIdx.x * 128;
    int tid = threadIdx.x;
    int pl = br * LL + l;
    for (int i = tid; i < 512; i += 192) scw[i] = convW[(size_t)pl * DD * KK + i];
    for (int i = tid; i < 128; i += 192) sb[i] = convb[pl * DD + i];
    __syncthreads();
    size_t rowbase = (size_t)(br * BB + b) * TT;
    const float LOG2E = 1.4426950408889634f;
    for (int i = tid; i < 16384; i += 192) {
        int r = i >> 7, d = i & 127;
        int t = t0 + r;
        float x0 = (t >= 3) ? g_xr[(rowbase + t - 3) * DD + d] : 0.f;
        float x1 = (t >= 2) ? g_xr[(rowbase + t - 2) * DD + d] : 0.f;
        float x2 = (t >= 1) ? g_xr[(rowbase + t - 1) * DD + d] : 0.f;
        float x3 = g_xr[(rowbase + t) * DD + d];
        float v = scw[d * 4 + 0] * x0 + scw[d * 4 + 1] * x1 + scw[d * 4 + 2] * x2
                + scw[d * 4 + 3] * x3 + sb[d];
        float uu = v / (1.f + ex2f(-v * LOG2E));
        g_u[(rowbase + t) * DD + d] = uu;
        sUt[d * 132 + r] = uu;
    }
    const float* Wb = xpW + (size_t)pl * 36 * DD;
    for (int i = tid; i < 4608; i += 192) {
        int e = i >> 7, k = i & 127;
        sW[k * 38 + e] = Wb[(size_t)e * DD + k];
    }
    __syncthreads();
    int rowg = tid & 31, colg = tid >> 5;
    u64 acc[4][3];
    #pragma unroll
    for (int r = 0; r < 4; r++)
        #pragma unroll
        for (int p = 0; p < 3; p++) acc[r][p] = 0ull;
    #pragma unroll 2
    for (int k = 0; k < 128; k++) {
        float4 h4 = *(const float4*)&sUt[k * 132 + rowg * 4];
        u64 w0 = *(const u64*)&sW[k * 38 + colg * 6];
        u64 w1 = *(const u64*)&sW[k * 38 + colg * 6 + 2];
        u64 w2 = *(const u64*)&sW[k * 38 + colg * 6 + 4];
        float hv[4] = {h4.x, h4.y, h4.z, h4.w};
        #pragma unroll
        for (int r = 0; r < 4; r++) {
            u64 hp = pk2(hv[r], hv[r]);
            fma2(acc[r][0], hp, w0);
            fma2(acc[r][1], hp, w1);
            fma2(acc[r][2], hp, w2);
        }
    }
    #pragma unroll
    for (int r = 0; r < 4; r++) {
        size_t ob = (rowbase + t0 + rowg * 4 + r) * 36 + colg * 6;
        #pragma unroll
        for (int p = 0; p < 3; p++) {
            float2 v = upk2(acc[r][p]);
            *(float2*)&g_xdbl[ob + 2 * p] = v;
        }
    }
}

// ---------------- k_scan1: per-chunk local scan (h_in = 0) + prefix products ----------------
// grid (CH, 128), block 128 (d)
__global__ void k_scan1(const float* __restrict__ A_log, const float* __restrict__ Dp_all,
                        const float* __restrict__ dtW, const float* __restrict__ dtb, int l) {
    __shared__ float sXD[CS * 36];
    int c = blockIdx.x, bb = blockIdx.y;
    int br = bb >> 5;
    int d = threadIdx.x;
    int pl = br * LL + l;
    const float LOG2E = 1.4426950408889634f;
    const float LN2 = 0.6931471805599453f;
    u64 a2[8];
    #pragma unroll
    for (int p = 0; p < 8; p++) {
        float lo = -__expf(A_log[(size_t)(pl * DD + d) * NN + 2 * p    ]) * LOG2E;
        float hi = -__expf(A_log[(size_t)(pl * DD + d) * NN + 2 * p + 1]) * LOG2E;
        a2[p] = pk2(lo, hi);
    }
    float dpv = Dp_all[pl * DD + d];
    const float* dw = dtW + (size_t)(pl * DD + d) * RR;
    float w0 = dw[0], w1 = dw[1], w2 = dw[2], w3 = dw[3];
    float db = dtb[pl * DD + d];
    u64 h2[8], P2[8];
    u64 one2 = pk2(1.f, 1.f);
    #pragma unroll
    for (int p = 0; p < 8; p++) { h2[p] = 0ull; P2[p] = one2; }
    size_t rowbase = (size_t)bb * TT + (size_t)c * CS;
    for (int i = d; i < CS * 36; i += 128)
        sXD[i] = g_xdbl[rowbase * 36 + i];
    __syncthreads();
    for (int s = 0; s < CS; s++) {
        const float* xd = &sXD[s * 36];
        float4 x4 = *(const float4*)xd;
        float dtp = w0 * x4.x + w1 * x4.y + w2 * x4.z + w3 * x4.w + db;
        float e = ex2f(dtp * LOG2E);
        float dt = (dtp > 15.f) ? dtp : LN2 * lg2f(1.f + e);
        float uv = g_u[(rowbase + s) * DD + d];
        float du = dt * uv;
        u64 du2 = pk2(du, du);
        u64 dt2 = pk2(dt, dt);
        float y = dpv * uv;
        u64 y2 = 0ull;
        #pragma unroll
        for (int p = 0; p < 8; p++) {
            u64 arg = mul2(dt2, a2[p]);
            float2 av = upk2(arg);
            u64 dA2 = pk2(ex2f(av.x), ex2f(av.y));
            u64 B2 = *(const u64*)&xd[4 + 2 * p];
            u64 C2 = *(const u64*)&xd[20 + 2 * p];
            u64 t2 = mul2(du2, B2);
            fma2(t2, dA2, h2[p]);
            h2[p] = t2;
            fma2(y2, t2, C2);
            P2[p] = mul2(P2[p], dA2);
        }
        float2 yv = upk2(y2);
        g_y[(rowbase + s) * DD + d] = y + yv.x + yv.y;
    }
    size_t sb = ((size_t)(bb * CH + c) * DD + d) * NN;
    #pragma unroll
    for (int p = 0; p < 8; p++) {
        float2 hv = upk2(h2[p]);
        float2 pv = upk2(P2[p]);
        *(float2*)&g_hfin[sb + 2 * p] = hv;
        *(float2*)&g_pfin[sb + 2 * p] = pv;
    }
}

// ---------------- k_scan2: sequential combine over chunks -> h_in per chunk ----------------
// 262144 threads, each owns one (bb,d,n) channel
__global__ void k_scan2() {
    int idx = blockIdx.x * 256 + threadIdx.x;     // (bb*128 + d)*16 + n
    int nd = idx & (DD * NN - 1);
    int bb = idx >> 11;
    size_t base = (size_t)bb * CH * DD * NN + nd;
    float h = 0.f;
    #pragma unroll
    for (int c = 0; c < CH; c++) {
        g_hin[base + (size_t)c * DD * NN] = h;
        h = g_pfin[base + (size_t)c * DD * NN] * h + g_hfin[base + (size_t)c * DD * NN];
    }
}

// ---------------- k_scan3: correction scan (c_t = dA_t c_{t-1}, c_0 = h_in) ----------------
// grid (CH-1, 128), chunk index = blockIdx.x + 1
__global__ void k_scan3(const float* __restrict__ A_log,
                        const float* __restrict__ dtW, const float* __restrict__ dtb, int l) {
    __shared__ float sXD[CS * 36];
    int c = blockIdx.x + 1, bb = blockIdx.y;
    int br = bb >> 5;
    int d = threadIdx.x;
    int pl = br * LL + l;
    const float LOG2E = 1.4426950408889634f;
    const float LN2 = 0.6931471805599453f;
    u64 a2[8];
    #pragma unroll
    for (int p = 0; p < 8; p++) {
        float lo = -__expf(A_log[(size_t)(pl * DD + d) * NN + 2 * p    ]) * LOG2E;
        float hi = -__expf(A_log[(size_t)(pl * DD + d) * NN + 2 * p + 1]) * LOG2E;
        a2[p] = pk2(lo, hi);
    }
    const float* dw = dtW + (size_t)(pl * DD + d) * RR;
    float w0 = dw[0], w1 = dw[1], w2 = dw[2], w3 = dw[3];
    float db = dtb[pl * DD + d];
    size_t sb = ((size_t)(bb * CH + c) * DD + d) * NN;
    u64 cs2[8];
    #pragma unroll
    for (int p = 0; p < 8; p++) cs2[p] = *(const u64*)&g_hin[sb + 2 * p];
    size_t rowbase = (size_t)bb * TT + (size_t)c * CS;
    for (int i = d; i < CS * 36; i += 128)
        sXD[i] = g_xdbl[rowbase * 36 + i];
    __syncthreads();
    for (int s = 0; s < CS; s++) {
        const float* xd = &sXD[s * 36];
        float4 x4 = *(const float4*)xd;
        float dtp = w0 * x4.x + w1 * x4.y + w2 * x4.z + w3 * x4.w + db;
        float e = ex2f(dtp * LOG2E);
        float dt = (dtp > 15.f) ? dtp : LN2 * lg2f(1.f + e);
        u64 dt2 = pk2(dt, dt);
        u64 y2 = 0ull;
        #pragma unroll
        for (int p = 0; p < 8; p++) {
            u64 arg = mul2(dt2, a2[p]);
            float2 av = upk2(arg);
            u64 dA2 = pk2(ex2f(av.x), ex2f(av.y));
            cs2[p] = mul2(dA2, cs2[p]);
            u64 C2 = *(const u64*)&xd[20 + 2 * p];
            fma2(y2, cs2[p], C2);
        }
        float2 yv = upk2(y2);
        g_y[(rowbase + s) * DD + d] += yv.x + yv.y;
    }
}

// ---------------- k_outgemm ----------------
__global__ void k_outgemm(const float* __restrict__ oW, int l, int dst) {
    extern __shared__ float sm[];
    float* sPt = sm;                 // [128][132]
    float* sW  = sm + 128 * 132;     // [128][66]
    int br = blockIdx.z, b = blockIdx.y, t0 = blockIdx.x * 128;
    int tid = threadIdx.x;
    const float LOG2E = 1.4426950408889634f;
    size_t base = ((size_t)(br * BB + b) * TT + t0) * DD;
    for (int i = tid; i < 16384; i += 256) {
        int r = i >> 7, dd = i & 127;
        float zv = g_z[base + i];
        float p = g_y[base + i] * zv / (1.f + ex2f(-zv * LOG2E));
        sPt[dd * 132 + r] = p;
    }
    const float* Wb = oW + (size_t)(br * LL + l) * HH * DD;
    for (int i = tid; i < 8192; i += 256) {
        int hh = i >> 7, k = i & 127;
        sW[k * 66 + hh] = Wb[(size_t)hh * DD + k];
    }
    __syncthreads();
    int rowg = tid & 31, colg = tid >> 5;
    u64 acc[4][4];
    #pragma unroll
    for (int r = 0; r < 4; r++)
        #pragma unroll
        for (int p = 0; p < 4; p++) acc[r][p] = 0ull;
    #pragma unroll 2
    for (int k = 0; k < 128; k++) {
        float4 h4 = *(const float4*)&sPt[k * 132 + rowg * 4];
        u64 w0 = *(const u64*)&sW[k * 66 + colg * 8];
        u64 w1 = *(const u64*)&sW[k * 66 + colg * 8 + 2];
        u64 w2 = *(const u64*)&sW[k * 66 + colg * 8 + 4];
        u64 w3 = *(const u64*)&sW[k * 66 + colg * 8 + 6];
        float hv[4] = {h4.x, h4.y, h4.z, h4.w};
        #pragma unroll
        for (int r = 0; r < 4; r++) {
            u64 hp = pk2(hv[r], hv[r]);
            fma2(acc[r][0], hp, w0);
            fma2(acc[r][1], hp, w1);
            fma2(acc[r][2], hp, w2);
            fma2(acc[r][3], hp, w3);
        }
    }
    float* hb = g_h[dst] + ((size_t)(br * BB + b) * TT + t0) * HH;
    #pragma unroll
    for (int r = 0; r < 4; r++) {
        int row = rowg * 4 + r;
        float2 p0 = upk2(acc[r][0]), p1 = upk2(acc[r][1]);
        float2 p2 = upk2(acc[r][2]), p3 = upk2(acc[r][3]);
        *(float4*)&hb[(size_t)row * HH + colg * 8]     = make_float4(p0.x, p0.y, p1.x, p1.y);
        *(float4*)&hb[(size_t)row * HH + colg * 8 + 4] = make_float4(p2.x, p2.y, p3.x, p3.y);
    }
}

// ---------------- k_head ----------------
__global__ void k_head(const float* __restrict__ opW, const float* __restrict__ opb,
                       float* __restrict__ out, int src) {
    __shared__ float sH[64 * 64];
    __shared__ float sW[64 * 33];
    __shared__ float sB[32];
    int br = blockIdx.z, b = blockIdx.y, t0 = blockIdx.x * 64;
    int tid = threadIdx.x;
    const float* hb = g_h[src] + ((size_t)(br * BB + b) * TT + t0) * HH;
    for (int i = tid; i < 4096; i += 256) sH[i] = hb[i];
    for (int i = tid; i < 2048; i += 256) {
        int e = i >> 6, hh = i & 63;
        sW[hh * 33 + e] = opW[(size_t)br * EE * HH + i];
    }
    if (tid < 32) sB[tid] = opb[br * EE + tid];
    __syncthreads();
    int e = tid & 31, rg = tid >> 5;
    #pragma unroll
    for (int i = 0; i < 8; i++) {
        int r = rg * 8 + i;
        float acc = sB[e];
        #pragma unroll
        for (int hh = 0; hh < 64; hh++) acc += sH[r * 64 + hh] * sW[hh * 33 + e];
        float z = tanhf(acc);
        float n2 = wsum(z * z);
        float n = sqrtf(fmaxf(n2, 1e-15f));
        float zh = z * (tanhf(n) / n);
        float n2b = wsum(zh * zh);
        float nb = sqrtf(fmaxf(n2b, 1e-15f));
        if (nb > MAXN) zh *= MAXN / nb;
        out[(size_t)br * BB * TT * EE + ((size_t)(b * TT + t0 + r)) * EE + e] = zh;
    }
}

// ---------------- k_mobius ----------------
__device__ __forceinline__ float mob(float x, float y) {
    float x2 = wsum(x * x);
    float y2 = wsum(y * y);
    float xy = wsum(x * y);
    float num = (1.f + 2.f * xy + y2) * x + (1.f - x2) * y;
    float den = 1.f + 2.f * xy + x2 * y2;
    return num / fmaxf(den, 1e-15f);
}

__global__ void k_mobius(float* __restrict__ out) {
    int warp = threadIdx.x >> 5, e = threadIdx.x & 31;
    size_t row = (size_t)blockIdx.x * 8 + warp;
    size_t S = (size_t)BB * TT * EE;
    float tv = out[0 * S + row * EE + e];
    float wv = out[1 * S + row * EE + e];
    float dv = out[2 * S + row * EE + e];
    float rv = out[3 * S + row * EE + e];
    float m = mob(wv, dv);
    m = mob(tv, m);
    m = mob(m, rv);
    float n2 = wsum(m * m);
    float n = sqrtf(fmaxf(n2, 1e-15f));
    if (n > MAXN) m *= MAXN / n;
    out[4 * S + row * EE + e] = m;
}

// ---------------- launch ----------------
extern "C" void kernel_launch(void* const* d_in, const int* in_sizes, int n_in,
                              void* d_out, int out_size) {
    const float* trend = (const float*)d_in[0];
    const float* sweek = (const float*)d_in[1];
    const float* sday  = (const float*)d_in[2];
    const float* resid = (const float*)d_in[3];
    const float* inp_W = (const float*)d_in[4];
    const float* inp_b = (const float*)d_in[5];
    const float* in_proj_W = (const float*)d_in[6];
    const float* conv_W = (const float*)d_in[7];
    const float* conv_b = (const float*)d_in[8];
    const float* xproj_W = (const float*)d_in[9];
    const float* dt_W = (const float*)d_in[10];
    const float* dt_b = (const float*)d_in[11];
    const float* A_log = (const float*)d_in[12];
    const float* D_skip = (const float*)d_in[13];
    const float* out_W = (const float*)d_in[14];
    const float* outp_W = (const float*)d_in[15];
    const float* outp_b = (const float*)d_in[16];
    float* out = (float*)d_out;

    const int SM_INPROJ = (64 * 68 + 64 * 132) * 4;
    const int SM_CONVXD = (128 * 132 + 128 * 38 + 512 + 128) * 4;
    const int SM_OUTG   = (128 * 132 + 128 * 66) * 4;
    cudaFuncSetAttribute(k_inproj,   cudaFuncAttributeMaxDynamicSharedMemorySize, SM_INPROJ);
    cudaFuncSetAttribute(k_convxdbl, cudaFuncAttributeMaxDynamicSharedMemorySize, SM_CONVXD);
    cudaFuncSetAttribute(k_outgemm,  cudaFuncAttributeMaxDynamicSharedMemorySize, SM_OUTG);

    k_embed<<<(BR * BB * TT * HH) / 256, 256>>>(trend, sweek, sday, resid, inp_W, inp_b);

    for (int l = 0; l < LL; l++) {
        int src = l & 1, dst = (l + 1) & 1;
        k_inproj<<<dim3(16, 32, 4), 256, SM_INPROJ>>>(in_proj_W, l, src);
        k_convxdbl<<<dim3(8, 32, 4), 192, SM_CONVXD>>>(conv_W, conv_b, xproj_W, l);
        k_scan1<<<dim3(CH, BR * BB), 128>>>(A_log, D_skip, dt_W, dt_b, l);
        k_scan2<<<(BR * BB * DD * NN) / 256, 256>>>();
        k_scan3<<<dim3(CH - 1, BR * BB), 128>>>(A_log, dt_W, dt_b, l);
        k_outgemm<<<dim3(8, 32, 4), 256, SM_OUTG>>>(out_W, l, dst);
    }

    k_head<<<dim3(16, 32, 4), 256>>>(outp_W, outp_b, out, LL & 1);
    k_mobius<<<(BB * TT) / 8, 256>>>(out);
}